// round 12
// baseline (speedup 1.0000x reference)
#include <cuda_runtime.h>
#include <math.h>

#define NELEM 16384
#define NB    16384
#define NBLK  128
#define NTHR  128
#define CAP   16
#define CSTRIDE 64   // 64 floats = 256B between chunk counters (distinct L2 slices)

typedef unsigned long long ull;

// Parity-double-buffered / monotone scratch: no cleanup pass, replay-safe.
__device__ float    g_bsum[2][NB];             // bucket sums (atomicAdd) — proven-safe bulk path
__device__ unsigned g_cnt[2][NB];              // bucket slot counts (atomicAdd)
__device__ float4   g_slot[NB * CAP];          // (time, exp, event, 0) — tie lists only
__device__ float    g_csum[2][NBLK * CSTRIDE]; // per-chunk totals (atomicAdd, padded)
__device__ float    g_accn[2], g_accd[2];      // loss accumulators (atomicAdd, parity)
__device__ ull      g_done;                    // monotone ticket; epoch = g_done >> 7
__device__ int      g_barcnt;                  // gbar counter (self-resetting)
__device__ int      g_sense;                   // gbar sense flag

static __device__ __forceinline__ ull ldv64(const ull* p) {
    ull v; asm volatile("ld.global.cg.u64 %0, [%1];" : "=l"(v) : "l"(p)); return v;
}
static __device__ __forceinline__ unsigned ldv32(const unsigned* p) {
    unsigned v; asm volatile("ld.global.cg.u32 %0, [%1];" : "=r"(v) : "l"(p)); return v;
}
static __device__ __forceinline__ float ldvf(const float* p) {
    float v; asm volatile("ld.global.cg.f32 %0, [%1];" : "=f"(v) : "l"(p)); return v;
}

static __device__ __forceinline__ int bucket_of(float t) {
    int b = (int)(t * 16384.0f);
    return b < 0 ? 0 : (b > NB - 1 ? NB - 1 : b);
}

// Proven sense-reversing grid barrier + NEW: nanosleep backoff in the waiter
// spin. Semantics identical; only the poll pressure on the L2 line changes.
__device__ __forceinline__ void gbar() {
    __threadfence();
    __syncthreads();
    if (threadIdx.x == 0) {
        volatile int* vs = &g_sense;
        int s = *vs;
        if (atomicAdd(&g_barcnt, 1) == NBLK - 1) {
            g_barcnt = 0;
            __threadfence();
            *vs = s ^ 1;
        } else {
            unsigned delay = 32;
            while (*vs == s) {
                __nanosleep(delay);
                if (delay < 256) delay <<= 1;
            }
        }
        __threadfence();
    }
    __syncthreads();
}

__global__ void __launch_bounds__(NTHR, 1) cox_kernel(
    const float* __restrict__ risk,
    const float* __restrict__ time,
    const float* __restrict__ event,
    float* __restrict__ out)
{
    const int t   = threadIdx.x;
    const int blk = blockIdx.x;
    const int i   = blk * NTHR + t;
    const int lane = t & 31, w = t >> 5;

    __shared__ float s_w[4];
    __shared__ float s_base;
    __shared__ float rn[4], rd[4];

    // ---- Front: quiescent epoch + inputs, all loads concurrent ------------
    const unsigned ep1 = (unsigned)(ldv64(&g_done) >> 7) + 1u;
    const int par = (int)(ep1 & 1u);
    const float my_t  = __ldg(&time[i]);
    const float my_ev = __ldg(&event[i]);
    const float my_e  = __expf(__ldg(&risk[i]));     // MUFU-direct
    const int   b     = bucket_of(my_t);

    // ---- Phase 1: histogram + chunk totals + slot scatter ------------------
    g_bsum[par ^ 1][i] = 0.0f;                       // prep next epoch
    g_cnt[par ^ 1][i]  = 0u;
    if (t == 0) {
        g_csum[par ^ 1][blk * CSTRIDE] = 0.0f;
        if (blk == 0) { g_accn[par ^ 1] = 0.0f; g_accd[par ^ 1] = 0.0f; }
    }
    atomicAdd(&g_bsum[par][b], my_e);                // exact bucket sum (proven path)
    atomicAdd(&g_csum[par][(b >> 7) * CSTRIDE], my_e); // chunk total, final pre-B1
    unsigned c = atomicAdd(&g_cnt[par][b], 1u);
    if (c < CAP) g_slot[b * CAP + c] = make_float4(my_t, my_e, my_ev, 0.0f);
    gbar();  // the ONLY grid barrier

    // ---- Phase 2: owner of bucket i; all loads issued up front (MLP) ------
    const float    bs  = ldvf(&g_bsum[par][i]);
    const unsigned cnt = ldv32(&g_cnt[par][i]);
    float4 sl0 = __ldcg(&g_slot[i * CAP + 0]);
    float4 sl1 = __ldcg(&g_slot[i * CAP + 1]);
    float4 sl2 = __ldcg(&g_slot[i * CAP + 2]);
    float4 sl3 = __ldcg(&g_slot[i * CAP + 3]);
    float csum0 = 0.0f, csum1 = 0.0f, csum2 = 0.0f, csum3 = 0.0f;
    if (w == 0) {   // warp 0 gathers all 128 chunk totals, 4 per lane
        csum0 = ldvf(&g_csum[par][(lane      ) * CSTRIDE]);
        csum1 = ldvf(&g_csum[par][(lane +  32) * CSTRIDE]);
        csum2 = ldvf(&g_csum[par][(lane +  64) * CSTRIDE]);
        csum3 = ldvf(&g_csum[par][(lane +  96) * CSTRIDE]);
    }

    // In-warp inclusive suffix scan of bucket sums
    float v = bs;
    #pragma unroll
    for (int d = 1; d < 32; d <<= 1) {
        float o = __shfl_down_sync(0xffffffffu, v, d);
        if (lane + d < 32) v += o;
    }
    if (lane == 0) s_w[w] = v;                       // warp total
    // Cross-chunk base: sum of chunk totals for chunks > blk (no barrier)
    if (w == 0) {
        float th = 0.0f;
        if ((lane      ) > blk) th += csum0;
        if ((lane +  32) > blk) th += csum1;
        if ((lane +  64) > blk) th += csum2;
        if ((lane +  96) > blk) th += csum3;
        #pragma unroll
        for (int o = 16; o > 0; o >>= 1) th += __shfl_down_sync(0xffffffffu, th, o);
        if (lane == 0) s_base = th;
    }
    __syncthreads();
    float hiW = 0.0f;
    #pragma unroll
    for (int k = 0; k < 4; k++) if (k > w) hiW += s_w[k];
    const float sb = s_base + (v - bs) + hiW;        // sum over buckets strictly > i

    // ---- Phase 3: per-element loss for my bucket (exact in-bucket ties) ---
    float num = 0.0f, den = 0.0f;
    if (cnt <= 4u) {                                 // register fast path (99.6%)
        const int len = (int)cnt;
        float tt[4] = {sl0.x, sl1.x, sl2.x, sl3.x};
        float ee[4] = {sl0.y, sl1.y, sl2.y, sl3.y};
        float vv[4] = {sl0.z, sl1.z, sl2.z, sl3.z};
        #pragma unroll
        for (int a = 0; a < 4; a++) {
            if (a < len && vv[a] != 0.0f) {
                float s = sb;
                #pragma unroll
                for (int m = 0; m < 4; m++)
                    if (m < len && tt[m] >= tt[a]) s += ee[m];
                num += __logf(ee[a] / s);            // = theta - log s
                den += 1.0f;
            }
        }
    } else if (cnt <= CAP) {                         // gmem path (rare, exact)
        const int len = (int)cnt;
        for (int a = 0; a < len; a++) {
            float4 pa = __ldcg(&g_slot[i * CAP + a]);
            if (pa.z != 0.0f) {
                float s = sb;
                for (int m = 0; m < len; m++) {
                    float4 pm = __ldcg(&g_slot[i * CAP + m]);
                    if (pm.x >= pa.x) s += pm.y;
                }
                num += __logf(pa.y / s);
                den += 1.0f;
            }
        }
    } else {                                         // overflow fallback (exact, ~never)
        for (int j = 0; j < NELEM; j++) {
            float tj = __ldg(&time[j]);
            if (bucket_of(tj) == i && __ldg(&event[j]) != 0.0f) {
                float s = sb;
                for (int m2 = 0; m2 < NELEM; m2++) {
                    float tm = __ldg(&time[m2]);
                    if (bucket_of(tm) == i && tm >= tj) s += __expf(__ldg(&risk[m2]));
                }
                num += __ldg(&risk[j]) - __logf(s);
                den += 1.0f;
            }
        }
    }

    // ---- Block reduce -> accumulator + ticket finalize --------------------
    #pragma unroll
    for (int o = 16; o > 0; o >>= 1) {
        num += __shfl_down_sync(0xffffffffu, num, o);
        den += __shfl_down_sync(0xffffffffu, den, o);
    }
    if (lane == 0) { rn[w] = num; rd[w] = den; }
    __syncthreads();
    if (t == 0) {
        float n = rn[0] + rn[1] + rn[2] + rn[3];
        float d = rd[0] + rd[1] + rd[2] + rd[3];
        atomicAdd(&g_accn[par], n);
        atomicAdd(&g_accd[par], d);
        __threadfence();
        ull old = atomicAdd(&g_done, 1ULL);
        if (old == ((ull)ep1 << 7) - 1ULL) {         // last arriver finalizes
            __threadfence();
            float tn = ldvf(&g_accn[par]);
            float td = ldvf(&g_accd[par]);
            out[0] = -tn / td;
        }
    }
}

extern "C" void kernel_launch(void* const* d_in, const int* in_sizes, int n_in,
                              void* d_out, int out_size) {
    const float* risk  = (const float*)d_in[0];
    const float* time  = (const float*)d_in[1];
    const float* event = (const float*)d_in[2];
    float* out = (float*)d_out;
    cox_kernel<<<NBLK, NTHR>>>(risk, time, event, out);
}

// round 13
// speedup vs baseline: 1.1404x; 1.1404x over previous
#include <cuda_runtime.h>
#include <math.h>

#define NELEM 16384
#define NB    16384
#define NBLK  128
#define NTHR  128
#define CAP   16
#define CSTRIDE 64        // 256B between chunk counters (distinct L2 slices)
#define NUM_SCALE 262144.0f   // 2^18 fixed-point scale for num
#define NUM_BIAS  (1LL << 31) // per-block bias so contributions are positive

typedef unsigned long long ull;

// Parity-double-buffered / monotone scratch: no cleanup pass, replay-safe.
__device__ float    g_bsum[2][NB];             // bucket sums (atomicAdd) — proven bulk path
__device__ unsigned g_cnt[2][NB];              // bucket slot counts (atomicAdd)
__device__ float4   g_slot[NB * CAP];          // (time, exp, event, 0) — tie lists only
__device__ float    g_csum[2][NBLK * CSTRIDE]; // per-chunk totals (atomicAdd, padded)
__device__ ull      g_acc[2];                  // fused tail: count|den|biased num (parity)
__device__ ull      g_bar;                     // monotone barrier counter: +NBLK per launch
__device__ ull      g_done;                    // epoch counter: +1 per launch (winner only)

static __device__ __forceinline__ ull ldv64(const ull* p) {
    ull v; asm volatile("ld.global.cg.u64 %0, [%1];" : "=l"(v) : "l"(p)); return v;
}
static __device__ __forceinline__ unsigned ldv32(const unsigned* p) {
    unsigned v; asm volatile("ld.global.cg.u32 %0, [%1];" : "=r"(v) : "l"(p)); return v;
}
static __device__ __forceinline__ float ldvf(const float* p) {
    float v; asm volatile("ld.global.cg.f32 %0, [%1];" : "=f"(v) : "l"(p)); return v;
}

static __device__ __forceinline__ int bucket_of(float t) {
    int b = (int)(t * 16384.0f);
    return b < 0 ? 0 : (b > NB - 1 ? NB - 1 : b);
}

__global__ void __launch_bounds__(NTHR, 1) cox_kernel(
    const float* __restrict__ risk,
    const float* __restrict__ time,
    const float* __restrict__ event,
    float* __restrict__ out)
{
    const int t   = threadIdx.x;
    const int blk = blockIdx.x;
    const int i   = blk * NTHR + t;
    const int lane = t & 31, w = t >> 5;

    __shared__ float s_w[4];
    __shared__ float s_base;
    __shared__ float rn[4], rd[4];

    // ---- Front: quiescent epoch + inputs, all loads concurrent ------------
    // g_done is bumped only by the winner at launch end -> stable for all
    // front reads (every front read happens-before B1, B1 before any bump).
    const unsigned ep1 = (unsigned)ldv64(&g_done) + 1u;
    const int par = (int)(ep1 & 1u);
    const float my_t  = __ldg(&time[i]);
    const float my_ev = __ldg(&event[i]);
    const float my_e  = __expf(__ldg(&risk[i]));     // MUFU-direct
    const int   b     = bucket_of(my_t);

    // ---- Phase 1: histogram + chunk totals + slot scatter (all atomic) ----
    atomicAdd(&g_bsum[par][b], my_e);                // exact bucket sum (proven path)
    atomicAdd(&g_csum[par][(b >> 7) * CSTRIDE], my_e); // chunk total, final pre-B1
    unsigned c = atomicAdd(&g_cnt[par][b], 1u);
    if (c < CAP) g_slot[b * CAP + c] = make_float4(my_t, my_e, my_ev, 0.0f);

    // ---- B1: monotone-counter grid barrier (no sense flip, 1 RT cheaper) --
    __threadfence();                                  // drain slot store + atomics
    __syncthreads();
    if (t == 0) {
        atomicAdd(&g_bar, 1ULL);
        const ull target = (ull)ep1 * (ull)NBLK;
        while (ldv64(&g_bar) < target) { }
        __threadfence();
    }
    __syncthreads();

    // ---- Phase 2: owner of bucket i; all loads issued up front (MLP) ------
    const float    bs  = ldvf(&g_bsum[par][i]);
    const unsigned cnt = ldv32(&g_cnt[par][i]);
    float4 sl0 = __ldcg(&g_slot[i * CAP + 0]);
    float4 sl1 = __ldcg(&g_slot[i * CAP + 1]);
    float4 sl2 = __ldcg(&g_slot[i * CAP + 2]);
    float4 sl3 = __ldcg(&g_slot[i * CAP + 3]);
    float csum0 = 0.0f, csum1 = 0.0f, csum2 = 0.0f, csum3 = 0.0f;
    if (w == 0) {   // warp 0 gathers all 128 chunk totals, 4 per lane
        csum0 = ldvf(&g_csum[par][(lane      ) * CSTRIDE]);
        csum1 = ldvf(&g_csum[par][(lane +  32) * CSTRIDE]);
        csum2 = ldvf(&g_csum[par][(lane +  64) * CSTRIDE]);
        csum3 = ldvf(&g_csum[par][(lane +  96) * CSTRIDE]);
    }

    // Next-epoch zeroing — post-barrier, off the critical path; nobody reads
    // par^1 this launch; cross-launch ordering makes it visible next replay.
    g_bsum[par ^ 1][i] = 0.0f;
    g_cnt[par ^ 1][i]  = 0u;
    if (t == 0) {
        g_csum[par ^ 1][blk * CSTRIDE] = 0.0f;
        if (blk == 0) g_acc[par ^ 1] = 0ULL;
    }

    // In-warp inclusive suffix scan of bucket sums
    float v = bs;
    #pragma unroll
    for (int d = 1; d < 32; d <<= 1) {
        float o = __shfl_down_sync(0xffffffffu, v, d);
        if (lane + d < 32) v += o;
    }
    if (lane == 0) s_w[w] = v;                       // warp total
    // Cross-chunk base: sum of chunk totals for chunks > blk (no barrier)
    if (w == 0) {
        float th = 0.0f;
        if ((lane      ) > blk) th += csum0;
        if ((lane +  32) > blk) th += csum1;
        if ((lane +  64) > blk) th += csum2;
        if ((lane +  96) > blk) th += csum3;
        #pragma unroll
        for (int o = 16; o > 0; o >>= 1) th += __shfl_down_sync(0xffffffffu, th, o);
        if (lane == 0) s_base = th;
    }
    __syncthreads();
    float hiW = 0.0f;
    #pragma unroll
    for (int k = 0; k < 4; k++) if (k > w) hiW += s_w[k];
    const float sb = s_base + (v - bs) + hiW;        // sum over buckets strictly > i

    // ---- Phase 3: per-element loss for my bucket (exact in-bucket ties) ---
    float num = 0.0f, den = 0.0f;
    if (cnt <= 4u) {                                 // register fast path (99.6%)
        const int len = (int)cnt;
        float tt[4] = {sl0.x, sl1.x, sl2.x, sl3.x};
        float ee[4] = {sl0.y, sl1.y, sl2.y, sl3.y};
        float vv[4] = {sl0.z, sl1.z, sl2.z, sl3.z};
        #pragma unroll
        for (int a = 0; a < 4; a++) {
            if (a < len && vv[a] != 0.0f) {
                float s = sb;
                #pragma unroll
                for (int m = 0; m < 4; m++)
                    if (m < len && tt[m] >= tt[a]) s += ee[m];
                num += __logf(ee[a] / s);            // = theta - log s
                den += 1.0f;
            }
        }
    } else if (cnt <= CAP) {                         // gmem path (rare, exact)
        const int len = (int)cnt;
        for (int a = 0; a < len; a++) {
            float4 pa = __ldcg(&g_slot[i * CAP + a]);
            if (pa.z != 0.0f) {
                float s = sb;
                for (int m = 0; m < len; m++) {
                    float4 pm = __ldcg(&g_slot[i * CAP + m]);
                    if (pm.x >= pa.x) s += pm.y;
                }
                num += __logf(pa.y / s);
                den += 1.0f;
            }
        }
    } else {                                         // overflow fallback (exact, ~never)
        for (int j = 0; j < NELEM; j++) {
            float tj = __ldg(&time[j]);
            if (bucket_of(tj) == i && __ldg(&event[j]) != 0.0f) {
                float s = sb;
                for (int m2 = 0; m2 < NELEM; m2++) {
                    float tm = __ldg(&time[m2]);
                    if (bucket_of(tm) == i && tm >= tj) s += __expf(__ldg(&risk[m2]));
                }
                num += __ldg(&risk[j]) - __logf(s);
                den += 1.0f;
            }
        }
    }

    // ---- Block reduce -> ONE fused atomic; last arriver owns the total ----
    #pragma unroll
    for (int o = 16; o > 0; o >>= 1) {
        num += __shfl_down_sync(0xffffffffu, num, o);
        den += __shfl_down_sync(0xffffffffu, den, o);
    }
    if (lane == 0) { rn[w] = num; rd[w] = den; }
    __syncthreads();
    if (t == 0) {
        float n = rn[0] + rn[1] + rn[2] + rn[3];
        float d = rd[0] + rd[1] + rd[2] + rd[3];
        // Pack: [63:56] arrival count, [55:41] den (integer), [40:0] biased num_fx.
        long long nfx = llrintf(n * NUM_SCALE);
        ull mine = (1ULL << 56)
                 | ((ull)(unsigned)(d + 0.5f) << 41)
                 | (ull)(nfx + NUM_BIAS);
        ull old = atomicAdd(&g_acc[par], mine);
        ull tot = old + mine;
        if ((tot >> 56) == (ull)NBLK) {              // I'm the last arriver
            long long tfx = (long long)(tot & ((1ULL << 41) - 1ULL))
                          - (long long)NBLK * NUM_BIAS;
            float tn = (float)tfx * (1.0f / NUM_SCALE);
            float td = (float)((tot >> 41) & 0x7FFFULL);
            out[0] = -tn / td;
            atomicAdd(&g_done, 1ULL);                // bump epoch (once per launch)
        }
    }
}

extern "C" void kernel_launch(void* const* d_in, const int* in_sizes, int n_in,
                              void* d_out, int out_size) {
    const float* risk  = (const float*)d_in[0];
    const float* time  = (const float*)d_in[1];
    const float* event = (const float*)d_in[2];
    float* out = (float*)d_out;
    cox_kernel<<<NBLK, NTHR>>>(risk, time, event, out);
}